// round 6
// baseline (speedup 1.0000x reference)
#include <cuda_runtime.h>

// Histogram2d: x[32,16384,64] f32 in [0,1) -> hist[32,128,64] * weights[128,64]
//
// Single fused kernel. Per-thread private u8 histograms in SMEM with a
// bank-aligned layout (lane l always hits bank l -> conflict-free RMWs).
// Blocks dump u16x2-packed partials to global scratch; the last block per
// batch (acq_rel atomic ticket, 128B-padded counters) reduces the partials,
// applies weights, writes output, and resets its ticket (graph-replay safe).

constexpr int B = 32, S = 16384, F = 64, BINS = 128;
constexpr int NCHUNK = 27;             // 26*608 + 576 = 16384; iters<=152 (u8-safe)
constexpr int CHUNK = 608;
constexpr int THREADS = 256;
// smem: 8 warps x 1024 words. word(w, m, l) = w*1024 + m*32 + l  (bank = l)
constexpr int SMEM_BYTES = 8 * 1024 * 4;           // 32768 B -> 6 blocks/SM

// u16x2-packed partials: word W = q*64 + f holds bins (2q, 2q+1) of feature f.
constexpr int PWORDS = (BINS / 2) * F;             // 4096 words per (chunk,batch)
__device__ __align__(16) unsigned int g_scratch[(size_t)NCHUNK * B * PWORDS];
// one counter per 128-byte line -> no same-line L2-atomic serialization
__device__ int g_count[B * 32];

__global__ __launch_bounds__(THREADS, 6)
void hist_kernel(const float* __restrict__ x, const float* __restrict__ wts,
                 float* __restrict__ out) {
    extern __shared__ unsigned int sh[];
    __shared__ int s_last;
    const int tid = threadIdx.x;
    const int w = tid >> 5, l = tid & 31;

    // zero own histogram: word (w, m, l) -> bank l, conflict-free
#pragma unroll
    for (int m = 0; m < 32; m++) sh[(w << 10) + (m << 5) + l] = 0u;

    unsigned char* sb = reinterpret_cast<unsigned char*>(sh);
    const unsigned int tbase = (w << 12) + (l << 2);   // byte base of this lane's hist

    const int fh = w & 1;        // feature half: 0 -> f 0..31, 1 -> f 32..63
    const int soff = w >> 1;     // row offset mod 4
    const int f = fh * 32 + l;
    const int b = blockIdx.y, c = blockIdx.x;

    const int row0 = c * CHUNK;
    const int rows = min(CHUNK, S - row0);   // 608 or 576
    const int iters = rows >> 2;             // 152 or 144 (both /8) -> u8 safe
    const float* base = x + (((size_t)b * S + row0 + soff) * F + f);

    constexpr int U = 8;                     // load-ahead for MLP
#pragma unroll 1
    for (int i = 0; i < iters; i += U) {
        float v[U];
#pragma unroll
        for (int u = 0; u < U; u++)
            v[u] = __ldcs(base + (size_t)(i + u) * (4 * F));
#pragma unroll
        for (int u = 0; u < U; u++) {
            // exact trunc(v*128): RZ-add truncates mantissa; bin bits = [16:23)
            const unsigned int bits = __float_as_uint(__fadd_rz(v[u], 1.0f));
            // byte offset ((bin>>2)<<7) | (bin&3): keeps this lane in bank l
            const unsigned int off = (((bits >> 18) & 31u) << 7) | ((bits >> 16) & 3u);
            sb[tbase + off] = (unsigned char)(sb[tbase + off] + 1);
        }
    }
    __syncthreads();

    // Intra-block reduction over 4 s-offsets (dp4a byte extraction),
    // u16x2-packed coalesced dump. Loads hit bank fl = lane -> conflict-free.
    unsigned int* outp = g_scratch + ((size_t)c * B + b) * PWORDS;
#pragma unroll
    for (int k = 0; k < 8; k++) {
        const int u = tid + THREADS * k;     // 0..2047
        const int fo = u & 63;
        const int m  = u >> 6;               // -> bins 4m..4m+3
        const int fh2 = fo >> 5, fl = fo & 31;
        unsigned int s0 = 0, s1 = 0, s2 = 0, s3 = 0;
#pragma unroll
        for (int s = 0; s < 4; s++) {
            const unsigned int v = sh[((2 * s + fh2) << 10) + (m << 5) + fl];
            s0 = __dp4a(v, 0x00000001u, s0);
            s1 = __dp4a(v, 0x00000100u, s1);
            s2 = __dp4a(v, 0x00010000u, s2);
            s3 = __dp4a(v, 0x01000000u, s3);
        }
        outp[(2 * m + 0) * F + fo] = s0 | (s1 << 16);   // bins 4m, 4m+1
        outp[(2 * m + 1) * F + fo] = s2 | (s3 << 16);   // bins 4m+2, 4m+3
    }

    // ---- ticket: acq_rel atomic (release = my dump visible; acquire = all
    // prior dumps visible to the winner). No gpu fence for non-winners. ----
    if (tid == 0) {
        int old;
        asm volatile("atom.add.acq_rel.gpu.global.s32 %0, [%1], 1;"
                     : "=r"(old) : "l"(&g_count[b * 32]) : "memory");
        s_last = (old == NCHUNK - 1);
    }
    __syncthreads();   // broadcasts s_last; orders reduce loads after the acquire
    if (!s_last) return;

    // Reduce batch b: 4096 words, 16 per thread; loads & stores coalesced.
    const unsigned int* sc = g_scratch + (size_t)b * PWORDS;
#pragma unroll 1
    for (int k = 0; k < 16; k++) {
        const int W = tid + THREADS * k;     // q*64 + f
        const int q = W >> 6, fo = W & 63;
        unsigned int a = 0;
#pragma unroll
        for (int c2 = 0; c2 < NCHUNK; c2++)
            a += sc[(size_t)c2 * B * PWORDS + W];        // packed u16x2, carry-free
        const float wlo = wts[(2 * q) * F + fo];
        const float whi = wts[(2 * q + 1) * F + fo];
        float* ob = out + ((size_t)b * BINS + 2 * q) * F + fo;
        ob[0] = (float)(a & 0xFFFFu) * wlo;
        ob[F] = (float)(a >> 16) * whi;
    }
    if (tid == 0) g_count[b * 32] = 0;       // reset for next graph replay
}

extern "C" void kernel_launch(void* const* d_in, const int* in_sizes, int n_in,
                              void* d_out, int out_size) {
    const float* x   = (const float*)d_in[0];
    const float* wts = (const float*)d_in[1];
    float* out = (float*)d_out;

    cudaFuncSetAttribute(hist_kernel, cudaFuncAttributeMaxDynamicSharedMemorySize, SMEM_BYTES);

    dim3 grid(NCHUNK, B);   // 27 x 32 = 864 blocks, single wave at occ 6
    hist_kernel<<<grid, THREADS, SMEM_BYTES>>>(x, wts, out);
}

// round 7
// speedup vs baseline: 1.5101x; 1.5101x over previous
#include <cuda_runtime.h>

// Histogram2d: x[32,16384,64] f32 in [0,1) -> hist[32,128,64] * weights[128,64]
//
// Two kernels (fusion regressed: rounds 5-6). Hist: per-thread private u8
// histograms in SMEM, bank-aligned layout (lane l always hits bank l ->
// conflict-free RMWs), zero atomics, u16x2-packed partial dump.
// Reduce v3: 8-way chunk split, 262K threads, fully-unrolled predicated
// loads, smem combine, weights applied at the end.

constexpr int B = 32, S = 16384, F = 64, BINS = 128;
constexpr int NCHUNK = 27;             // 26*608 + 576 = 16384; iters<=152 (u8-safe)
constexpr int CHUNK = 608;
constexpr int THREADS = 256;
// smem: 8 warps x 1024 words. word(w, m, l) = w*1024 + m*32 + l  (bank = l)
constexpr int SMEM_BYTES = 8 * 1024 * 4;           // 32768 B -> 6 blocks/SM

// u16x2-packed partials: word W = q*64 + f holds bins (2q, 2q+1) of feature f.
constexpr int PWORDS = (BINS / 2) * F;             // 4096 words per (chunk,batch)
__device__ __align__(16) unsigned int g_scratch[(size_t)NCHUNK * B * PWORDS];

__global__ __launch_bounds__(THREADS, 6)
void hist_kernel(const float* __restrict__ x) {
    extern __shared__ unsigned int sh[];
    const int tid = threadIdx.x;
    const int w = tid >> 5, l = tid & 31;

    // zero own histogram: word (w, m, l) -> bank l, conflict-free
#pragma unroll
    for (int m = 0; m < 32; m++) sh[(w << 10) + (m << 5) + l] = 0u;

    unsigned char* sb = reinterpret_cast<unsigned char*>(sh);
    const unsigned int tbase = (w << 12) + (l << 2);   // byte base of this lane's hist

    const int fh = w & 1;        // feature half: 0 -> f 0..31, 1 -> f 32..63
    const int soff = w >> 1;     // row offset mod 4
    const int f = fh * 32 + l;
    const int b = blockIdx.y, c = blockIdx.x;

    const int row0 = c * CHUNK;
    const int rows = min(CHUNK, S - row0);   // 608 or 576
    const int iters = rows >> 2;             // 152 or 144 (both /8) -> u8 safe
    const float* base = x + (((size_t)b * S + row0 + soff) * F + f);

    constexpr int U = 8;                     // load-ahead for MLP
#pragma unroll 1
    for (int i = 0; i < iters; i += U) {
        float v[U];
#pragma unroll
        for (int u = 0; u < U; u++)
            v[u] = __ldcs(base + (size_t)(i + u) * (4 * F));
#pragma unroll
        for (int u = 0; u < U; u++) {
            // exact trunc(v*128): RZ-add truncates mantissa; bin bits = [16:23)
            const unsigned int bits = __float_as_uint(__fadd_rz(v[u], 1.0f));
            // byte offset ((bin>>2)<<7) | (bin&3): keeps this lane in bank l
            const unsigned int off = (((bits >> 18) & 31u) << 7) | ((bits >> 16) & 3u);
            sb[tbase + off] = (unsigned char)(sb[tbase + off] + 1);
        }
    }
    __syncthreads();

    // Intra-block reduction over 4 s-offsets (dp4a byte extraction),
    // u16x2-packed coalesced dump. Loads hit bank fl = lane -> conflict-free.
    unsigned int* outp = g_scratch + ((size_t)c * B + b) * PWORDS;
#pragma unroll
    for (int k = 0; k < 8; k++) {
        const int u = tid + THREADS * k;     // 0..2047
        const int fo = u & 63;
        const int m  = u >> 6;               // -> bins 4m..4m+3
        const int fh2 = fo >> 5, fl = fo & 31;
        unsigned int s0 = 0, s1 = 0, s2 = 0, s3 = 0;
#pragma unroll
        for (int s = 0; s < 4; s++) {
            const unsigned int v = sh[((2 * s + fh2) << 10) + (m << 5) + fl];
            s0 = __dp4a(v, 0x00000001u, s0);
            s1 = __dp4a(v, 0x00000100u, s1);
            s2 = __dp4a(v, 0x00010000u, s2);
            s3 = __dp4a(v, 0x01000000u, s3);
        }
        outp[(2 * m + 0) * F + fo] = s0 | (s1 << 16);   // bins 4m, 4m+1
        outp[(2 * m + 1) * F + fo] = s2 | (s3 << 16);   // bins 4m+2, 4m+3
    }
}

__global__ __launch_bounds__(THREADS)
void reduce_kernel(const float* __restrict__ wts, float* __restrict__ out) {
    // 8-way chunk split per output group + smem combine.
    // idx: f4i[0:4) cq[4:7) p[7:13) b[13:18)  -> 262144 threads, 1024 blocks
    const int idx = blockIdx.x * THREADS + threadIdx.x;
    const int tid = threadIdx.x;
    const int f4 = (idx & 15) << 2;          // 4-float feature group
    const int cq = (idx >> 4) & 7;           // chunk octet
    const int p  = (idx >> 7) & 63;          // bin pair -> bins 2p, 2p+1
    const int b  = idx >> 13;

    const int c0 = cq * 4;
    unsigned int a0 = 0, a1 = 0, a2 = 0, a3 = 0;
#pragma unroll
    for (int j = 0; j < 4; j++) {            // constant trips -> full unroll, MLP 4
        const int c = c0 + j;
        if (c < NCHUNK) {                    // predicated (cq==6: 3, cq==7: 0 live)
            const uint4 v = __ldg(reinterpret_cast<const uint4*>(
                g_scratch + ((size_t)(c * B + b)) * PWORDS + p * F + f4));
            a0 += v.x; a1 += v.y; a2 += v.z; a3 += v.w;   // packed u16x2, carry-free
        }
    }
    __shared__ uint4 s4[THREADS];
    s4[tid] = make_uint4(a0, a1, a2, a3);
    __syncthreads();

    if (cq == 0) {
#pragma unroll
        for (int j = 1; j < 8; j++) {
            const uint4 q = s4[tid + 16 * j];
            a0 += q.x; a1 += q.y; a2 += q.z; a3 += q.w;
        }
        const float4 wlo = *reinterpret_cast<const float4*>(wts + (2 * p) * F + f4);
        const float4 whi = *reinterpret_cast<const float4*>(wts + (2 * p + 1) * F + f4);
        float4 olo, ohi;
        olo.x = (float)(a0 & 0xFFFFu) * wlo.x;  ohi.x = (float)(a0 >> 16) * whi.x;
        olo.y = (float)(a1 & 0xFFFFu) * wlo.y;  ohi.y = (float)(a1 >> 16) * whi.y;
        olo.z = (float)(a2 & 0xFFFFu) * wlo.z;  ohi.z = (float)(a2 >> 16) * whi.z;
        olo.w = (float)(a3 & 0xFFFFu) * wlo.w;  ohi.w = (float)(a3 >> 16) * whi.w;
        float* ob = out + ((size_t)b * BINS + 2 * p) * F + f4;
        *reinterpret_cast<float4*>(ob)     = olo;
        *reinterpret_cast<float4*>(ob + F) = ohi;
    }
}

extern "C" void kernel_launch(void* const* d_in, const int* in_sizes, int n_in,
                              void* d_out, int out_size) {
    const float* x   = (const float*)d_in[0];
    const float* wts = (const float*)d_in[1];
    float* out = (float*)d_out;

    cudaFuncSetAttribute(hist_kernel, cudaFuncAttributeMaxDynamicSharedMemorySize, SMEM_BYTES);

    dim3 grid(NCHUNK, B);   // 27 x 32 = 864 blocks, single wave at occ 6
    hist_kernel<<<grid, THREADS, SMEM_BYTES>>>(x);
    reduce_kernel<<<(B * 64 * 8 * 16) / THREADS, THREADS>>>(wts, out);
}

// round 8
// speedup vs baseline: 1.6947x; 1.1223x over previous
#include <cuda_runtime.h>

// Histogram2d: x[32,16384,64] f32 in [0,1) -> hist[32,128,64] * weights[128,64]
//
// Two kernels. Hist: 512-thread blocks (16 warps = 2 feature-halves x 8
// row-offsets), per-thread private u8 histograms in SMEM, bank-aligned
// (lane l always hits bank l -> conflict-free RMWs), zero atomics.
// Scratch halved vs round 7: 13 chunks x 6.8MB of u16x2-packed partials.

constexpr int B = 32, S = 16384, F = 64, BINS = 128;
constexpr int NCHUNK = 13;             // 12*1280 + 1024 = 16384
constexpr int CHUNK = 1280;            // iters = 160/128 <= 255 (u8-safe), /8 exact
constexpr int THREADS = 512;           // 16 warps: fh = w&1, soff = w>>1 (0..7)
// smem: 16 warps x 1024 words. word(w, m, l) = w*1024 + m*32 + l  (bank = l)
constexpr int SMEM_BYTES = 16 * 1024 * 4;          // 65536 B -> 3 blocks/SM (48 warps)

// u16x2-packed partials: word W = q*64 + f holds bins (2q, 2q+1) of feature f.
constexpr int PWORDS = (BINS / 2) * F;             // 4096 words per (chunk,batch)
__device__ __align__(16) unsigned int g_scratch[(size_t)NCHUNK * B * PWORDS];  // 6.8 MB

__global__ __launch_bounds__(THREADS, 3)
void hist_kernel(const float* __restrict__ x) {
    extern __shared__ unsigned int sh[];
    const int tid = threadIdx.x;
    const int w = tid >> 5, l = tid & 31;

    // zero own histogram: word (w, m, l) -> bank l, conflict-free
#pragma unroll
    for (int m = 0; m < 32; m++) sh[(w << 10) + (m << 5) + l] = 0u;

    unsigned char* sb = reinterpret_cast<unsigned char*>(sh);
    const unsigned int tbase = (w << 12) + (l << 2);   // byte base of this lane's hist

    const int fh = w & 1;        // feature half: 0 -> f 0..31, 1 -> f 32..63
    const int soff = w >> 1;     // row offset mod 8
    const int f = fh * 32 + l;
    const int b = blockIdx.y, c = blockIdx.x;

    const int row0 = c * CHUNK;
    const int rows = min(CHUNK, S - row0);   // 1280 or 1024
    const int iters = rows >> 3;             // 160 or 128 (/8 exact) -> u8 safe
    const float* base = x + (((size_t)b * S + row0 + soff) * F + f);

    constexpr int U = 8;                     // load-ahead for MLP
#pragma unroll 1
    for (int i = 0; i < iters; i += U) {
        float v[U];
#pragma unroll
        for (int u = 0; u < U; u++)
            v[u] = __ldcs(base + (size_t)(i + u) * (8 * F));
#pragma unroll
        for (int u = 0; u < U; u++) {
            // exact trunc(v*128): RZ-add truncates mantissa; bin bits = [16:23)
            const unsigned int bits = __float_as_uint(__fadd_rz(v[u], 1.0f));
            // byte offset ((bin>>2)<<7) | (bin&3): keeps this lane in bank l
            const unsigned int off = (((bits >> 18) & 31u) << 7) | ((bits >> 16) & 3u);
            sb[tbase + off] = (unsigned char)(sb[tbase + off] + 1);
        }
    }
    __syncthreads();

    // Intra-block reduction over 8 row-offsets (dp4a byte extraction),
    // u16x2-packed coalesced dump. Per-bin partial <= 8*160 = 1280 < 2^16.
    // smem loads hit bank fl = lane -> conflict-free.
    unsigned int* outp = g_scratch + ((size_t)c * B + b) * PWORDS;
#pragma unroll
    for (int k = 0; k < 4; k++) {
        const int u = tid + THREADS * k;     // 0..2047
        const int fo = u & 63;
        const int m  = u >> 6;               // -> bins 4m..4m+3
        const int fh2 = fo >> 5, fl = fo & 31;
        unsigned int s0 = 0, s1 = 0, s2 = 0, s3 = 0;
#pragma unroll
        for (int s = 0; s < 8; s++) {
            const unsigned int v = sh[((2 * s + fh2) << 10) + (m << 5) + fl];
            s0 = __dp4a(v, 0x00000001u, s0);
            s1 = __dp4a(v, 0x00000100u, s1);
            s2 = __dp4a(v, 0x00010000u, s2);
            s3 = __dp4a(v, 0x01000000u, s3);
        }
        outp[(2 * m + 0) * F + fo] = s0 | (s1 << 16);   // bins 4m, 4m+1
        outp[(2 * m + 1) * F + fo] = s2 | (s3 << 16);   // bins 4m+2, 4m+3
    }
}

__global__ __launch_bounds__(256)
void reduce_kernel(const float* __restrict__ wts, float* __restrict__ out) {
    // 2-way chunk split per output group + smem combine.
    // idx: f4i[0:4) cq[4] p[5:11) b[11:16)  -> 65536 threads, 256 blocks
    const int idx = blockIdx.x * 256 + threadIdx.x;
    const int tid = threadIdx.x;
    const int f4 = (idx & 15) << 2;          // 4-float feature group
    const int cq = (idx >> 4) & 1;           // chunk half
    const int p  = (idx >> 5) & 63;          // bin pair -> bins 2p, 2p+1
    const int b  = idx >> 11;

    const int c0 = cq * 7;                   // 7 or 6 live chunks
    unsigned int a0 = 0, a1 = 0, a2 = 0, a3 = 0;
#pragma unroll
    for (int j = 0; j < 7; j++) {            // constant trips -> full unroll, MLP 7
        const int c = c0 + j;
        if (c < NCHUNK) {
            const uint4 v = __ldg(reinterpret_cast<const uint4*>(
                g_scratch + ((size_t)(c * B + b)) * PWORDS + p * F + f4));
            a0 += v.x; a1 += v.y; a2 += v.z; a3 += v.w;   // packed u16x2, carry-free
        }
    }
    __shared__ uint4 s4[256];
    s4[tid] = make_uint4(a0, a1, a2, a3);
    __syncthreads();

    if (cq == 0) {
        const uint4 q = s4[tid + 16];
        a0 += q.x; a1 += q.y; a2 += q.z; a3 += q.w;
        const float4 wlo = *reinterpret_cast<const float4*>(wts + (2 * p) * F + f4);
        const float4 whi = *reinterpret_cast<const float4*>(wts + (2 * p + 1) * F + f4);
        float4 olo, ohi;
        olo.x = (float)(a0 & 0xFFFFu) * wlo.x;  ohi.x = (float)(a0 >> 16) * whi.x;
        olo.y = (float)(a1 & 0xFFFFu) * wlo.y;  ohi.y = (float)(a1 >> 16) * whi.y;
        olo.z = (float)(a2 & 0xFFFFu) * wlo.z;  ohi.z = (float)(a2 >> 16) * whi.z;
        olo.w = (float)(a3 & 0xFFFFu) * wlo.w;  ohi.w = (float)(a3 >> 16) * whi.w;
        float* ob = out + ((size_t)b * BINS + 2 * p) * F + f4;
        *reinterpret_cast<float4*>(ob)     = olo;
        *reinterpret_cast<float4*>(ob + F) = ohi;
    }
}

extern "C" void kernel_launch(void* const* d_in, const int* in_sizes, int n_in,
                              void* d_out, int out_size) {
    const float* x   = (const float*)d_in[0];
    const float* wts = (const float*)d_in[1];
    float* out = (float*)d_out;

    cudaFuncSetAttribute(hist_kernel, cudaFuncAttributeMaxDynamicSharedMemorySize, SMEM_BYTES);

    dim3 grid(NCHUNK, B);   // 13 x 32 = 416 blocks, single wave at occ 3
    hist_kernel<<<grid, THREADS, SMEM_BYTES>>>(x);
    reduce_kernel<<<65536 / 256, 256>>>(wts, out);
}